// round 13
// baseline (speedup 1.0000x reference)
#include <cuda_runtime.h>
#include <cuda_bf16.h>
#include <math.h>

#define N_ANCH   102400
#define FMP      320
#define NCLS     80
#define TOPK     1000
#define CAP      4096
#define NBINS    65536
#define NPART    64
#define NBLK     148
#define NWARPS   (NBLK * 32)
#define STAGE    192             // rows staged in shared for NMS

// libdevice precise expf — the exact function XLA:GPU links for HLO exp(f32).
extern "C" __device__ float __nv_expf(float);

// ------- state that must be zero at the start of every replay (ONE memset) --
struct GState {
    unsigned int hist[NBINS];
    unsigned int bars[8];
    unsigned int nzmask[32];     // 1000-bit bitmap of rows with nonzero mask
    int          count;
    int          nnz;
};
__device__ GState g;

// ------- scratch fully written-before-read each replay -----------------------
__device__ __align__(16) unsigned int      d_sbits[N_ANCH];
__device__ unsigned char                   d_label[N_ANCH];
__device__ unsigned long long              d_keys[CAP];
__device__ float4                          d_boxes4[TOPK];
__device__ int                             d_tlab[TOPK];
__device__ int                             d_rowslot[TOPK];
__device__ unsigned int                    d_rowdata[TOPK * 32];
__device__ int                             d_thresh;

// XLA LogisticExpander: logistic(x) = 1/(1+exp(-x)), exp->__nv_expf, div->rn.
__device__ __forceinline__ float xsig(float x) {
    return __fdiv_rn(1.0f, __fadd_rn(1.0f, __nv_expf(-x)));
}
__device__ __forceinline__ float xfused(float h, float K) {
    return __fsqrt_rn(__fmul_rn(xsig(h), K));
}

// ---------------- K1: per-anchor score/label + histogram --------------------
// EXACT revert to the proven R10 version: hist atomic only (bits>>16 spreads
// across thousands of bins). The R11/R12 part-atomic (bits>>26) serialized on
// ~1 address and cost ~50us — removed.
__global__ void k_score(const float* __restrict__ hmp,
                        const float* __restrict__ iou) {
    int a    = (blockIdx.x << 3) + (threadIdx.x >> 5);   // one warp per anchor
    int lane = threadIdx.x & 31;
    const float4* row = reinterpret_cast<const float4*>(hmp) + (size_t)a * 20;

    float4 v = make_float4(0.f, 0.f, 0.f, 0.f);
    float m = __int_as_float(0xff800000);
    if (lane < 20) {
        v = row[lane];
        m = fmaxf(fmaxf(v.x, v.y), fmaxf(v.z, v.w));
    }
    #pragma unroll
    for (int off = 16; off; off >>= 1)
        m = fmaxf(m, __shfl_xor_sync(0xffffffffu, m, off));

    float K   = xsig(iou[a]);
    float thr = m - 1e-4f;

    float best = __int_as_float(0xff800000);
    int   bi   = 0x7FFFFFFF;
    if (lane < 20) {
        int b = lane * 4;
        if (v.x >= thr) { float f = xfused(v.x, K); if (f > best) { best = f; bi = b;     } }
        if (v.y >= thr) { float f = xfused(v.y, K); if (f > best) { best = f; bi = b + 1; } }
        if (v.z >= thr) { float f = xfused(v.z, K); if (f > best) { best = f; bi = b + 2; } }
        if (v.w >= thr) { float f = xfused(v.w, K); if (f > best) { best = f; bi = b + 3; } }
    }
    #pragma unroll
    for (int off = 16; off; off >>= 1) {
        float of = __shfl_xor_sync(0xffffffffu, best, off);
        int   oi = __shfl_xor_sync(0xffffffffu, bi,   off);
        if (of > best || (of == best && oi < bi)) { best = of; bi = oi; }
    }

    if (lane == 0) {
        unsigned bits = __float_as_uint(best);
        d_sbits[a] = bits;
        d_label[a] = (unsigned char)bi;
        atomicAdd(&g.hist[bits >> 16], 1u);
    }
}

// ---------------- software grid barrier (all 148 blocks resident) -----------
__device__ __forceinline__ void gbar(int which) {
    __syncthreads();
    if (threadIdx.x == 0) {
        __threadfence();
        unsigned arrived = atomicAdd(&g.bars[which], 1u) + 1u;
        if (arrived < NBLK) {
            volatile unsigned* c = &g.bars[which];
            while (*c < NBLK) __nanosleep(32);
        }
        __threadfence();
    }
    __syncthreads();
}

// ---------------- K2: mega — threshold/compact/rank/mask/nms ----------------
__global__ void __launch_bounds__(1024, 1)
k_mega(const float* __restrict__ reg, float* __restrict__ out) {
    __shared__ unsigned spart[NPART];
    __shared__ unsigned wtot[32];
    __shared__ unsigned whi[32];
    __shared__ int      s_pstar;
    __shared__ unsigned s_above;
    __shared__ int      sslot[TOPK];
    __shared__ unsigned sstage[STAGE * 32];
    __shared__ unsigned skeep[32];

    const int tid  = threadIdx.x;
    const int blk  = blockIdx.x;
    const int gt   = blk * 1024 + tid;
    const int lane = tid & 31;
    const int wid  = tid >> 5;

    // ---- S2 prefetch (all blocks): one uint4 per thread, held in registers --
    uint4 pf = make_uint4(0u, 0u, 0u, 0u);
    bool  haspf = (gt < N_ANCH / 4);
    if (haspf) pf = reinterpret_cast<const uint4*>(d_sbits)[gt];

    // ======== S1 (block 0 only): exact 16-bit threshold from histogram ======
    if (blk == 0) {
        // part sums: warp w handles parts 2w, 2w+1; 8 uint4 (32 bins) per lane
        #pragma unroll
        for (int q = 0; q < 2; ++q) {
            int p = wid * 2 + q;
            const uint4* h4 = reinterpret_cast<const uint4*>(g.hist + (p << 10));
            unsigned s = 0;
            #pragma unroll
            for (int k = 0; k < 8; ++k) {
                uint4 vv = h4[lane * 8 + k];
                s += vv.x + vv.y + vv.z + vv.w;
            }
            #pragma unroll
            for (int off = 16; off; off >>= 1)
                s += __shfl_xor_sync(0xffffffffu, s, off);
            if (lane == 0) spart[p] = s;
        }
        __syncthreads();
        if (tid < 32) {
            unsigned a = spart[tid], b = spart[tid + 32];
            unsigned sa = a, sb = b;
            #pragma unroll
            for (int off = 1; off < 32; off <<= 1) {
                unsigned ta = __shfl_down_sync(0xffffffffu, sa, off);
                unsigned tb = __shfl_down_sync(0xffffffffu, sb, off);
                if (tid + off < 32) { sa += ta; sb += tb; }
            }
            unsigned totb = __shfl_sync(0xffffffffu, sb, 0);
            unsigned sufa = sa + totb;           // inclusive suffix at p=tid
            unsigned sufb = sb;                  // inclusive suffix at p=tid+32
            if (sufa >= TOPK && sufa - a < TOPK) { s_pstar = tid;      s_above = sufa - a; }
            if (sufb >= TOPK && sufb - b < TOPK) { s_pstar = tid + 32; s_above = sufb - b; }
        }
        __syncthreads();
        int base = s_pstar << 10;
        unsigned own = g.hist[base + tid];
        unsigned s = own;
        #pragma unroll
        for (int off = 1; off < 32; off <<= 1) {
            unsigned t = __shfl_down_sync(0xffffffffu, s, off);
            if (lane + off < 32) s += t;
        }
        if (lane == 0) wtot[wid] = s;
        __syncthreads();
        if (tid < 32) {
            unsigned v = wtot[tid];
            unsigned sv = v;
            #pragma unroll
            for (int off = 1; off < 32; off <<= 1) {
                unsigned t = __shfl_down_sync(0xffffffffu, sv, off);
                if (tid + off < 32) sv += t;
            }
            whi[tid] = sv - v;                   // totals of warps above mine
        }
        __syncthreads();
        unsigned tot = s_above + whi[wid] + s;   // count of scores >= this bin
        if (tot >= TOPK && tot - own < TOPK) d_thresh = base + tid;
    }
    gbar(0);

    // ======== S2: compact candidates (from prefetched registers) ============
    if (haspf) {
        int th = d_thresh;
        unsigned a = (unsigned)gt * 4u;
        #pragma unroll
        for (int q = 0; q < 4; ++q) {
            unsigned bits = (q == 0) ? pf.x : (q == 1) ? pf.y : (q == 2) ? pf.z : pf.w;
            if ((int)(bits >> 16) >= th) {
                int pos = atomicAdd(&g.count, 1);
                if (pos < CAP) {
                    unsigned long long key =
                        ((unsigned long long)bits << 32) |
                        (unsigned long long)(0xFFFFFFFFu - (a + q));
                    d_keys[pos] = ~key;
                }
            }
        }
    }
    gbar(1);

    // ======== S3: rank-by-counting + decode ==================================
    {
        int M = g.count; if (M > CAP) M = CAP;
        int cand = gt >> 4;
        int sub  = gt & 15;
        if (cand < M) {
            unsigned long long key = d_keys[cand];
            int rank = 0;
            for (int k = sub; k < M; k += 16)
                rank += (d_keys[k] < key) ? 1 : 0;
            rank += __shfl_xor_sync(0xffffffffu, rank, 1);
            rank += __shfl_xor_sync(0xffffffffu, rank, 2);
            rank += __shfl_xor_sync(0xffffffffu, rank, 4);
            rank += __shfl_xor_sync(0xffffffffu, rank, 8);

            if (sub == 0 && rank < TOPK) {
                unsigned long long k0 = ~key;
                unsigned bits = (unsigned)(k0 >> 32);
                unsigned aidx = 0xFFFFFFFFu - (unsigned)(k0 & 0xFFFFFFFFull);
                float score = __uint_as_float(bits);
                int   lab   = (int)d_label[aidx];

                const float CLAMPF = 6.907755278982137f;   // log(1000)
                float4 r4 = reinterpret_cast<const float4*>(reg)[aidx];
                float e0 = __nv_expf(fminf(r4.x, CLAMPF));
                float e1 = __nv_expf(fminf(r4.y, CLAMPF));
                float e2 = __nv_expf(fminf(r4.z, CLAMPF));
                float e3 = __nv_expf(fminf(r4.w, CLAMPF));
                float ax = (float)(aidx % FMP);
                float ay = (float)(aidx / FMP);
                float b0 = fminf(1.0f, fmaxf(0.0f, __fdiv_rn(__fmul_rn(__fadd_rn(ax, -e0), 4.0f), 1280.0f)));
                float b1 = fminf(1.0f, fmaxf(0.0f, __fdiv_rn(__fmul_rn(__fadd_rn(ay, -e1), 4.0f), 1280.0f)));
                float b2 = fminf(1.0f, fmaxf(0.0f, __fdiv_rn(__fmul_rn(__fadd_rn(ax,  e2), 4.0f), 1280.0f)));
                float b3 = fminf(1.0f, fmaxf(0.0f, __fdiv_rn(__fmul_rn(__fadd_rn(ay,  e3), 4.0f), 1280.0f)));

                out[rank]        = score;
                out[TOPK + rank] = (float)lab;
                reinterpret_cast<float4*>(out + 2 * TOPK)[rank] = make_float4(b0, b1, b2, b3);
                d_boxes4[rank] = make_float4(b0, b1, b2, b3);
                d_tlab[rank]   = lab;
            }
        }
    }
    gbar(2);

    // ======== S4: suppression rows, warp-per-row, compacted ==================
    {
        int gw = (blk << 5) + wid;                 // global warp id
        for (int i = gw; i < TOPK; i += NWARPS) {
            float4 bxi = d_boxes4[i];
            float ai = __fmul_rn(__fadd_rn(bxi.z, -bxi.x), __fadd_rn(bxi.w, -bxi.y));
            int li = d_tlab[i];

            unsigned myword = 0u;
            for (int c = (i >> 5); c < 32; ++c) {  // chunks < i>>5 never read
                int j = (c << 5) + lane;
                bool sup = false;
                if (j < TOPK && j > i && d_tlab[j] == li) {
                    float4 bxj = d_boxes4[j];
                    float aj = __fmul_rn(__fadd_rn(bxj.z, -bxj.x), __fadd_rn(bxj.w, -bxj.y));
                    float wd = fmaxf(1e-10f, __fadd_rn(fminf(bxi.z, bxj.z), -fmaxf(bxi.x, bxj.x)));
                    float hd = fmaxf(1e-10f, __fadd_rn(fminf(bxi.w, bxj.w), -fmaxf(bxi.y, bxj.y)));
                    float inter = __fmul_rn(wd, hd);
                    float den = __fadd_rn(__fadd_rn(__fadd_rn(ai, aj), -inter), 1e-10f);
                    // rn32(inter/den) > 0.6f <=> inter/den > midpoint(0.6f,nextup)
                    sup = ((double)inter / (double)den) > 0.6000000536441802978515625;
                }
                unsigned b = __ballot_sync(0xffffffffu, sup);
                if (lane == c) myword = b;
            }
            if (__ballot_sync(0xffffffffu, myword != 0u)) {
                int slot = 0;
                if (lane == 0) {
                    slot = atomicAdd(&g.nnz, 1);
                    d_rowslot[i] = slot;
                    atomicOr(&g.nzmask[i >> 5], 1u << (i & 31));
                }
                slot = __shfl_sync(0xffffffffu, slot, 0);
                d_rowdata[slot * 32 + lane] = myword;
            }
        }
    }
    gbar(3);

    // ======== S5: greedy NMS over compact rows (block 0) =====================
    if (blk != 0) return;
    {
        int nnz = g.nnz;
        int stagen = nnz < STAGE ? nnz : STAGE;
        for (int t = tid; t < stagen * 32; t += 1024) sstage[t] = d_rowdata[t];
        for (int t = tid; t < TOPK; t += 1024)        sslot[t]  = d_rowslot[t];
        __syncthreads();

        if (tid < 32) {
            unsigned keep = 0xFFFFFFFFu;         // lane ln holds keep bits [ln*32..]
            unsigned nzm  = g.nzmask[lane];
            for (int wi = 0; wi < 32; ++wi) {
                unsigned bits = __shfl_sync(0xffffffffu, nzm, wi);
                while (bits) {
                    int bpos = __ffs(bits) - 1;
                    bits &= bits - 1u;
                    unsigned kw = __shfl_sync(0xffffffffu, keep, wi);
                    if ((kw >> bpos) & 1u) {
                        int i = wi * 32 + bpos;
                        int slot = sslot[i];     // shared, warp-uniform
                        unsigned roww = (slot < STAGE) ? sstage[slot * 32 + lane]
                                                       : d_rowdata[slot * 32 + lane];
                        keep &= ~roww;
                    }
                }
            }
            skeep[lane] = keep;
        }
        __syncthreads();
        if (tid < TOPK)
            out[6 * TOPK + tid] = (float)((skeep[tid >> 5] >> (tid & 31)) & 1u);
    }
}

// ---------------- launch ----------------
extern "C" void kernel_launch(void* const* d_in, const int* in_sizes, int n_in,
                              void* d_out, int out_size) {
    const float* hmp = (const float*)d_in[0];
    const float* reg = (const float*)d_in[1];
    const float* iou = (const float*)d_in[2];
    float* out = (float*)d_out;

    void* gptr = nullptr;
    cudaGetSymbolAddress(&gptr, g);
    cudaMemsetAsync(gptr, 0, sizeof(GState), 0);

    k_score<<<N_ANCH / 8, 256>>>(hmp, iou);
    k_mega<<<NBLK, 1024>>>(reg, out);
}

// round 15
// speedup vs baseline: 2.1854x; 2.1854x over previous
#include <cuda_runtime.h>
#include <cuda_bf16.h>
#include <math.h>

#define N_ANCH   102400
#define FMP      320
#define NCLS     80
#define TOPK     1000
#define CAP      4096
#define NBINS    65536
#define NPART    64
#define NBLK     148
#define STAGE    192             // rows staged in shared for NMS

// libdevice precise expf — the exact function XLA:GPU links for HLO exp(f32).
extern "C" __device__ float __nv_expf(float);

// ------- state that must be zero at the start of every replay (ONE memset) --
struct GState {
    unsigned int hist[NBINS];
    unsigned int bars[8];
    unsigned int nzmask[32];     // 1000-bit bitmap of rows with nonzero mask
    int          count;
    int          nnz;
};
__device__ GState g;

// ------- scratch fully written-before-read each replay -----------------------
__device__ __align__(16) unsigned int      d_sbits[N_ANCH];
__device__ unsigned char                   d_label[N_ANCH];
__device__ unsigned long long              d_keys[CAP];
__device__ float4                          d_boxes4[TOPK];
__device__ int                             d_tlab[TOPK];
__device__ int                             d_rowslot[TOPK];
__device__ unsigned int                    d_rowdata[TOPK * 32];
__device__ unsigned int                    d_part[NPART];
__device__ int                             d_thresh;

// XLA LogisticExpander: logistic(x) = 1/(1+exp(-x)), exp->__nv_expf, div->rn.
__device__ __forceinline__ float xsig(float x) {
    return __fdiv_rn(1.0f, __fadd_rn(1.0f, __nv_expf(-x)));
}
__device__ __forceinline__ float xfused(float h, float K) {
    return __fsqrt_rn(__fmul_rn(xsig(h), K));
}

// ---------------- K1: per-anchor score/label + histogram --------------------
// VERBATIM the R10 version measured at ~27us inside the 86.5us run.
__global__ void k_score(const float* __restrict__ hmp,
                        const float* __restrict__ iou) {
    int a    = (blockIdx.x << 3) + (threadIdx.x >> 5);   // one warp per anchor
    int lane = threadIdx.x & 31;
    const float4* row = reinterpret_cast<const float4*>(hmp) + (size_t)a * 20;

    float4 v = make_float4(0.f, 0.f, 0.f, 0.f);
    float m = __int_as_float(0xff800000);
    if (lane < 20) {
        v = row[lane];
        m = fmaxf(fmaxf(v.x, v.y), fmaxf(v.z, v.w));
    }
    #pragma unroll
    for (int off = 16; off; off >>= 1)
        m = fmaxf(m, __shfl_xor_sync(0xffffffffu, m, off));

    float K   = xsig(iou[a]);
    float thr = m - 1e-4f;

    float best = __int_as_float(0xff800000);
    int   bi   = 0x7FFFFFFF;
    if (lane < 20) {
        int b = lane * 4;
        if (v.x >= thr) { float f = xfused(v.x, K); if (f > best) { best = f; bi = b;     } }
        if (v.y >= thr) { float f = xfused(v.y, K); if (f > best) { best = f; bi = b + 1; } }
        if (v.z >= thr) { float f = xfused(v.z, K); if (f > best) { best = f; bi = b + 2; } }
        if (v.w >= thr) { float f = xfused(v.w, K); if (f > best) { best = f; bi = b + 3; } }
    }
    #pragma unroll
    for (int off = 16; off; off >>= 1) {
        float of = __shfl_xor_sync(0xffffffffu, best, off);
        int   oi = __shfl_xor_sync(0xffffffffu, bi,   off);
        if (of > best || (of == best && oi < bi)) { best = of; bi = oi; }
    }

    if (lane == 0) {
        unsigned bits = __float_as_uint(best);
        d_sbits[a] = bits;
        d_label[a] = (unsigned char)bi;
        atomicAdd(&g.hist[bits >> 16], 1u);
    }
}

// ---------------- software grid barrier (all 148 blocks resident) -----------
__device__ __forceinline__ void gbar(int which) {
    __syncthreads();
    if (threadIdx.x == 0) {
        __threadfence();
        unsigned arrived = atomicAdd(&g.bars[which], 1u) + 1u;
        if (arrived < NBLK) {
            volatile unsigned* c = &g.bars[which];
            while (*c < NBLK) __nanosleep(32);
        }
        __threadfence();
    }
    __syncthreads();
}

// ---------------- K2: mega — partsum/threshold/compact/rank/mask/nms --------
// Structure is VERBATIM the R12 mega (measured 40.1us), with its g.part input
// replaced by the R10-proven distributed S0 stage writing d_part.
__global__ void __launch_bounds__(1024, 1)
k_mega(const float* __restrict__ reg, float* __restrict__ out) {
    __shared__ unsigned spart[NPART];
    __shared__ unsigned wtot[32];
    __shared__ unsigned whi[32];
    __shared__ int      s_pstar;
    __shared__ unsigned s_above;
    __shared__ unsigned tmp[32];
    __shared__ int      sslot[TOPK];
    __shared__ unsigned sstage[STAGE * 32];
    __shared__ unsigned skeep[32];

    const int tid  = threadIdx.x;
    const int blk  = blockIdx.x;
    const int gt   = blk * 1024 + tid;
    const int lane = tid & 31;

    // ======== S0: per-part histogram sums (blocks 0..63) — R10-proven =======
    if (blk < NPART) {
        unsigned v = g.hist[blk * 1024 + tid];
        #pragma unroll
        for (int off = 16; off; off >>= 1) v += __shfl_xor_sync(0xffffffffu, v, off);
        if ((tid & 31) == 0) wtot[tid >> 5] = v;
        __syncthreads();
        if (tid < 32) {
            unsigned w = wtot[tid];
            #pragma unroll
            for (int off = 16; off; off >>= 1) w += __shfl_xor_sync(0xffffffffu, w, off);
            if (tid == 0) d_part[blk] = w;
        }
    }
    gbar(0);

    // ======== S1: exact 16-bit threshold (block 0, fully parallel) ==========
    if (blk == 0) {
        if (tid < NPART) spart[tid] = d_part[tid];
        __syncthreads();
        if (tid < 32) {
            unsigned a = spart[tid], b = spart[tid + 32];
            unsigned sa = a, sb = b;
            #pragma unroll
            for (int off = 1; off < 32; off <<= 1) {
                unsigned ta = __shfl_down_sync(0xffffffffu, sa, off);
                unsigned tb = __shfl_down_sync(0xffffffffu, sb, off);
                if (tid + off < 32) { sa += ta; sb += tb; }
            }
            unsigned totb = __shfl_sync(0xffffffffu, sb, 0);
            unsigned sufa = sa + totb;           // inclusive suffix at p=tid
            unsigned sufb = sb;                  // inclusive suffix at p=tid+32
            if (sufa >= TOPK && sufa - a < TOPK) { s_pstar = tid;      s_above = sufa - a; }
            if (sufb >= TOPK && sufb - b < TOPK) { s_pstar = tid + 32; s_above = sufb - b; }
        }
        __syncthreads();
        int base = s_pstar << 10;
        int w = tid >> 5;
        unsigned own = g.hist[base + tid];
        unsigned s = own;
        #pragma unroll
        for (int off = 1; off < 32; off <<= 1) {
            unsigned t = __shfl_down_sync(0xffffffffu, s, off);
            if (lane + off < 32) s += t;
        }
        if (lane == 0) wtot[w] = s;
        __syncthreads();
        if (tid < 32) {
            unsigned v = wtot[tid];
            unsigned sv = v;
            #pragma unroll
            for (int off = 1; off < 32; off <<= 1) {
                unsigned t = __shfl_down_sync(0xffffffffu, sv, off);
                if (tid + off < 32) sv += t;
            }
            whi[tid] = sv - v;                   // totals of warps above mine
        }
        __syncthreads();
        unsigned tot = s_above + whi[w] + s;     // count of scores >= this bin
        if (tot >= TOPK && tot - own < TOPK) d_thresh = base + tid;
    }
    gbar(1);

    // ======== S2: compact candidates =========================================
    {
        int th = d_thresh;
        for (int t = gt; t < N_ANCH / 4; t += NBLK * 1024) {
            uint4 s = reinterpret_cast<const uint4*>(d_sbits)[t];
            unsigned a = (unsigned)t * 4u;
            #pragma unroll
            for (int q = 0; q < 4; ++q) {
                unsigned bits = (q == 0) ? s.x : (q == 1) ? s.y : (q == 2) ? s.z : s.w;
                if ((int)(bits >> 16) >= th) {
                    int pos = atomicAdd(&g.count, 1);
                    if (pos < CAP) {
                        unsigned long long key =
                            ((unsigned long long)bits << 32) |
                            (unsigned long long)(0xFFFFFFFFu - (a + q));
                        d_keys[pos] = ~key;
                    }
                }
            }
        }
    }
    gbar(2);

    // ======== S3: rank-by-counting + decode ==================================
    {
        int M = g.count; if (M > CAP) M = CAP;
        int cand = gt >> 4;
        int sub  = gt & 15;
        if (cand < M) {
            unsigned long long key = d_keys[cand];
            int rank = 0;
            for (int k = sub; k < M; k += 16)
                rank += (d_keys[k] < key) ? 1 : 0;
            rank += __shfl_xor_sync(0xffffffffu, rank, 1);
            rank += __shfl_xor_sync(0xffffffffu, rank, 2);
            rank += __shfl_xor_sync(0xffffffffu, rank, 4);
            rank += __shfl_xor_sync(0xffffffffu, rank, 8);

            if (sub == 0 && rank < TOPK) {
                unsigned long long k0 = ~key;
                unsigned bits = (unsigned)(k0 >> 32);
                unsigned aidx = 0xFFFFFFFFu - (unsigned)(k0 & 0xFFFFFFFFull);
                float score = __uint_as_float(bits);
                int   lab   = (int)d_label[aidx];

                const float CLAMPF = 6.907755278982137f;   // log(1000)
                float4 r4 = reinterpret_cast<const float4*>(reg)[aidx];
                float e0 = __nv_expf(fminf(r4.x, CLAMPF));
                float e1 = __nv_expf(fminf(r4.y, CLAMPF));
                float e2 = __nv_expf(fminf(r4.z, CLAMPF));
                float e3 = __nv_expf(fminf(r4.w, CLAMPF));
                float ax = (float)(aidx % FMP);
                float ay = (float)(aidx / FMP);
                float b0 = fminf(1.0f, fmaxf(0.0f, __fdiv_rn(__fmul_rn(__fadd_rn(ax, -e0), 4.0f), 1280.0f)));
                float b1 = fminf(1.0f, fmaxf(0.0f, __fdiv_rn(__fmul_rn(__fadd_rn(ay, -e1), 4.0f), 1280.0f)));
                float b2 = fminf(1.0f, fmaxf(0.0f, __fdiv_rn(__fmul_rn(__fadd_rn(ax,  e2), 4.0f), 1280.0f)));
                float b3 = fminf(1.0f, fmaxf(0.0f, __fdiv_rn(__fmul_rn(__fadd_rn(ay,  e3), 4.0f), 1280.0f)));

                out[rank]        = score;
                out[TOPK + rank] = (float)lab;
                reinterpret_cast<float4*>(out + 2 * TOPK)[rank] = make_float4(b0, b1, b2, b3);
                d_boxes4[rank] = make_float4(b0, b1, b2, b3);
                d_tlab[rank]   = lab;
            }
        }
    }
    gbar(3);

    // ======== S4: suppression rows, compacted (block-per-row, R12-proven) ====
    for (int i = blk; i < TOPK; i += NBLK) {
        int j = tid; int w = tid >> 5;
        float4 bxi = d_boxes4[i];
        float ai = __fmul_rn(__fadd_rn(bxi.z, -bxi.x), __fadd_rn(bxi.w, -bxi.y));
        int li = d_tlab[i];

        bool sup = false;
        if (j < TOPK && j > i && d_tlab[j] == li) {
            float4 bxj = d_boxes4[j];
            float aj = __fmul_rn(__fadd_rn(bxj.z, -bxj.x), __fadd_rn(bxj.w, -bxj.y));
            float wd = fmaxf(1e-10f, __fadd_rn(fminf(bxi.z, bxj.z), -fmaxf(bxi.x, bxj.x)));
            float hd = fmaxf(1e-10f, __fadd_rn(fminf(bxi.w, bxj.w), -fmaxf(bxi.y, bxj.y)));
            float inter = __fmul_rn(wd, hd);
            float den = __fadd_rn(__fadd_rn(__fadd_rn(ai, aj), -inter), 1e-10f);
            // rn32(inter/den) > 0.6f  <=>  inter/den > midpoint(0.6f, nextup(0.6f))
            sup = ((double)inter / (double)den) > 0.6000000536441802978515625;
        }
        unsigned b = __ballot_sync(0xffffffffu, sup);
        if ((j & 31) == 0) tmp[w] = b;
        __syncthreads();
        if (tid < 32) {
            unsigned x = tmp[tid];
            unsigned anyb = __ballot_sync(0xffffffffu, x != 0u);
            if (anyb) {
                int slot = 0;
                if (tid == 0) {
                    slot = atomicAdd(&g.nnz, 1);
                    d_rowslot[i] = slot;
                    atomicOr(&g.nzmask[i >> 5], 1u << (i & 31));
                }
                slot = __shfl_sync(0xffffffffu, slot, 0);
                d_rowdata[slot * 32 + tid] = x;
            }
        }
        __syncthreads();
    }
    gbar(4);

    // ======== S5: greedy NMS over compact rows (block 0) =====================
    if (blk != 0) return;
    {
        int nnz = g.nnz;
        int stagen = nnz < STAGE ? nnz : STAGE;
        for (int t = tid; t < stagen * 32; t += 1024) sstage[t] = d_rowdata[t];
        for (int t = tid; t < TOPK; t += 1024)        sslot[t]  = d_rowslot[t];
        __syncthreads();

        if (tid < 32) {
            unsigned keep = 0xFFFFFFFFu;         // lane ln holds keep bits [ln*32..]
            unsigned nzm  = g.nzmask[lane];
            for (int wi = 0; wi < 32; ++wi) {
                unsigned bits = __shfl_sync(0xffffffffu, nzm, wi);
                while (bits) {
                    int bpos = __ffs(bits) - 1;
                    bits &= bits - 1u;
                    unsigned kw = __shfl_sync(0xffffffffu, keep, wi);
                    if ((kw >> bpos) & 1u) {
                        int i = wi * 32 + bpos;
                        int slot = sslot[i];     // shared, warp-uniform
                        unsigned roww = (slot < STAGE) ? sstage[slot * 32 + lane]
                                                       : d_rowdata[slot * 32 + lane];
                        keep &= ~roww;
                    }
                }
            }
            skeep[lane] = keep;
        }
        __syncthreads();
        if (tid < TOPK)
            out[6 * TOPK + tid] = (float)((skeep[tid >> 5] >> (tid & 31)) & 1u);
    }
}

// ---------------- launch ----------------
extern "C" void kernel_launch(void* const* d_in, const int* in_sizes, int n_in,
                              void* d_out, int out_size) {
    const float* hmp = (const float*)d_in[0];
    const float* reg = (const float*)d_in[1];
    const float* iou = (const float*)d_in[2];
    float* out = (float*)d_out;

    void* gptr = nullptr;
    cudaGetSymbolAddress(&gptr, g);
    cudaMemsetAsync(gptr, 0, sizeof(GState), 0);

    k_score<<<N_ANCH / 8, 256>>>(hmp, iou);
    k_mega<<<NBLK, 1024>>>(reg, out);
}

// round 16
// speedup vs baseline: 2.3140x; 1.0589x over previous
#include <cuda_runtime.h>
#include <cuda_bf16.h>
#include <math.h>

#define N_ANCH   102400
#define FMP      320
#define NCLS     80
#define TOPK     1000
#define CAP      4096
#define NBINS    65536
#define NPART    64
#define NBLK     148
#define STAGE    192             // rows staged in shared for NMS

// libdevice precise expf — the exact function XLA:GPU links for HLO exp(f32).
extern "C" __device__ float __nv_expf(float);

// ------- state that must be zero at the start of every replay (ONE memset) --
struct GState {
    unsigned int hist[NBINS];
    unsigned int bars[8];
    unsigned int nzmask[32];     // 1000-bit bitmap of rows with nonzero mask
    int          count;
    int          nnz;
};
__device__ GState g;

// ------- scratch fully written-before-read each replay -----------------------
__device__ __align__(16) unsigned int      d_sbits[N_ANCH];
__device__ unsigned char                   d_label[N_ANCH];
__device__ unsigned long long              d_keys[CAP];
__device__ float4                          d_boxes4[TOPK];
__device__ int                             d_tlab[TOPK];
__device__ int                             d_rowslot[TOPK];
__device__ unsigned int                    d_rowdata[TOPK * 32];
__device__ unsigned int                    d_part[NPART];
__device__ int                             d_thresh;

// XLA LogisticExpander: logistic(x) = 1/(1+exp(-x)), exp->__nv_expf, div->rn.
__device__ __forceinline__ float xsig(float x) {
    return __fdiv_rn(1.0f, __fadd_rn(1.0f, __nv_expf(-x)));
}
__device__ __forceinline__ float xfused(float h, float K) {
    return __fsqrt_rn(__fmul_rn(xsig(h), K));
}

// ---------------- K1: scores — 8 anchors/warp, 4 lanes/anchor ---------------
// Full lane utilization; 2-round segmented reduces (shfl_xor 1,2 stay inside
// the aligned 4-lane group). Candidate arithmetic bit-identical to R10/R15.
__global__ void __launch_bounds__(256)
k_score(const float* __restrict__ hmp, const float* __restrict__ iou) {
    const int wid  = threadIdx.x >> 5;            // warp in block: 0..7
    const int lane = threadIdx.x & 31;
    const int grp  = lane >> 2;                   // anchor group 0..7
    const int sub  = lane & 3;                    // lane within group
    const int base = (blockIdx.x << 6) + (wid << 3);   // 8 anchors per warp
    const int a    = base + grp;

    // iou for the 8 anchors: lanes 0..7 load, broadcast to groups
    float iv = 0.0f;
    if (lane < 8) iv = iou[base + lane];
    float ivg = __shfl_sync(0xffffffffu, iv, grp);

    // each lane: 5 float4 = 20 classes [sub*20, sub*20+20)
    const float4* row = reinterpret_cast<const float4*>(hmp) + (size_t)a * 20 + sub * 5;
    float4 v0 = row[0], v1 = row[1], v2 = row[2], v3 = row[3], v4 = row[4];

    float m = fmaxf(fmaxf(v0.x, v0.y), fmaxf(v0.z, v0.w));
    m = fmaxf(m, fmaxf(fmaxf(v1.x, v1.y), fmaxf(v1.z, v1.w)));
    m = fmaxf(m, fmaxf(fmaxf(v2.x, v2.y), fmaxf(v2.z, v2.w)));
    m = fmaxf(m, fmaxf(fmaxf(v3.x, v3.y), fmaxf(v3.z, v3.w)));
    m = fmaxf(m, fmaxf(fmaxf(v4.x, v4.y), fmaxf(v4.z, v4.w)));
    m = fmaxf(m, __shfl_xor_sync(0xffffffffu, m, 1));
    m = fmaxf(m, __shfl_xor_sync(0xffffffffu, m, 2));

    float K   = xsig(ivg);
    float thr = m - 1e-4f;

    float best = __int_as_float(0xff800000);
    int   bi   = 0x7FFFFFFF;
    const int cb = sub * 20;
    #define CHK(val, idx) \
        if ((val) >= thr) { float f = xfused((val), K); \
                            if (f > best) { best = f; bi = cb + (idx); } }
    CHK(v0.x, 0)  CHK(v0.y, 1)  CHK(v0.z, 2)  CHK(v0.w, 3)
    CHK(v1.x, 4)  CHK(v1.y, 5)  CHK(v1.z, 6)  CHK(v1.w, 7)
    CHK(v2.x, 8)  CHK(v2.y, 9)  CHK(v2.z, 10) CHK(v2.w, 11)
    CHK(v3.x, 12) CHK(v3.y, 13) CHK(v3.z, 14) CHK(v3.w, 15)
    CHK(v4.x, 16) CHK(v4.y, 17) CHK(v4.z, 18) CHK(v4.w, 19)
    #undef CHK

    #pragma unroll
    for (int off = 1; off <= 2; off <<= 1) {
        float of = __shfl_xor_sync(0xffffffffu, best, off);
        int   oi = __shfl_xor_sync(0xffffffffu, bi,   off);
        if (of > best || (of == best && oi < bi)) { best = of; bi = oi; }
    }

    if (sub == 0) {
        unsigned bits = __float_as_uint(best);
        d_sbits[a] = bits;
        d_label[a] = (unsigned char)bi;
        atomicAdd(&g.hist[bits >> 16], 1u);
    }
}

// ---------------- software grid barrier (all 148 blocks resident) -----------
__device__ __forceinline__ void gbar(int which) {
    __syncthreads();
    if (threadIdx.x == 0) {
        __threadfence();
        unsigned arrived = atomicAdd(&g.bars[which], 1u) + 1u;
        if (arrived < NBLK) {
            volatile unsigned* c = &g.bars[which];
            while (*c < NBLK) __nanosleep(32);
        }
        __threadfence();
    }
    __syncthreads();
}

// ---------------- K2: mega — VERBATIM R15 (measured 28.8us) -----------------
__global__ void __launch_bounds__(1024, 1)
k_mega(const float* __restrict__ reg, float* __restrict__ out) {
    __shared__ unsigned spart[NPART];
    __shared__ unsigned wtot[32];
    __shared__ unsigned whi[32];
    __shared__ int      s_pstar;
    __shared__ unsigned s_above;
    __shared__ unsigned tmp[32];
    __shared__ int      sslot[TOPK];
    __shared__ unsigned sstage[STAGE * 32];
    __shared__ unsigned skeep[32];

    const int tid  = threadIdx.x;
    const int blk  = blockIdx.x;
    const int gt   = blk * 1024 + tid;
    const int lane = tid & 31;

    // ======== S0: per-part histogram sums (blocks 0..63) =====================
    if (blk < NPART) {
        unsigned v = g.hist[blk * 1024 + tid];
        #pragma unroll
        for (int off = 16; off; off >>= 1) v += __shfl_xor_sync(0xffffffffu, v, off);
        if ((tid & 31) == 0) wtot[tid >> 5] = v;
        __syncthreads();
        if (tid < 32) {
            unsigned w = wtot[tid];
            #pragma unroll
            for (int off = 16; off; off >>= 1) w += __shfl_xor_sync(0xffffffffu, w, off);
            if (tid == 0) d_part[blk] = w;
        }
    }
    gbar(0);

    // ======== S1: exact 16-bit threshold (block 0, fully parallel) ==========
    if (blk == 0) {
        if (tid < NPART) spart[tid] = d_part[tid];
        __syncthreads();
        if (tid < 32) {
            unsigned a = spart[tid], b = spart[tid + 32];
            unsigned sa = a, sb = b;
            #pragma unroll
            for (int off = 1; off < 32; off <<= 1) {
                unsigned ta = __shfl_down_sync(0xffffffffu, sa, off);
                unsigned tb = __shfl_down_sync(0xffffffffu, sb, off);
                if (tid + off < 32) { sa += ta; sb += tb; }
            }
            unsigned totb = __shfl_sync(0xffffffffu, sb, 0);
            unsigned sufa = sa + totb;           // inclusive suffix at p=tid
            unsigned sufb = sb;                  // inclusive suffix at p=tid+32
            if (sufa >= TOPK && sufa - a < TOPK) { s_pstar = tid;      s_above = sufa - a; }
            if (sufb >= TOPK && sufb - b < TOPK) { s_pstar = tid + 32; s_above = sufb - b; }
        }
        __syncthreads();
        int base = s_pstar << 10;
        int w = tid >> 5;
        unsigned own = g.hist[base + tid];
        unsigned s = own;
        #pragma unroll
        for (int off = 1; off < 32; off <<= 1) {
            unsigned t = __shfl_down_sync(0xffffffffu, s, off);
            if (lane + off < 32) s += t;
        }
        if (lane == 0) wtot[w] = s;
        __syncthreads();
        if (tid < 32) {
            unsigned v = wtot[tid];
            unsigned sv = v;
            #pragma unroll
            for (int off = 1; off < 32; off <<= 1) {
                unsigned t = __shfl_down_sync(0xffffffffu, sv, off);
                if (tid + off < 32) sv += t;
            }
            whi[tid] = sv - v;                   // totals of warps above mine
        }
        __syncthreads();
        unsigned tot = s_above + whi[w] + s;     // count of scores >= this bin
        if (tot >= TOPK && tot - own < TOPK) d_thresh = base + tid;
    }
    gbar(1);

    // ======== S2: compact candidates =========================================
    {
        int th = d_thresh;
        for (int t = gt; t < N_ANCH / 4; t += NBLK * 1024) {
            uint4 s = reinterpret_cast<const uint4*>(d_sbits)[t];
            unsigned a = (unsigned)t * 4u;
            #pragma unroll
            for (int q = 0; q < 4; ++q) {
                unsigned bits = (q == 0) ? s.x : (q == 1) ? s.y : (q == 2) ? s.z : s.w;
                if ((int)(bits >> 16) >= th) {
                    int pos = atomicAdd(&g.count, 1);
                    if (pos < CAP) {
                        unsigned long long key =
                            ((unsigned long long)bits << 32) |
                            (unsigned long long)(0xFFFFFFFFu - (a + q));
                        d_keys[pos] = ~key;
                    }
                }
            }
        }
    }
    gbar(2);

    // ======== S3: rank-by-counting + decode ==================================
    {
        int M = g.count; if (M > CAP) M = CAP;
        int cand = gt >> 4;
        int sub  = gt & 15;
        if (cand < M) {
            unsigned long long key = d_keys[cand];
            int rank = 0;
            for (int k = sub; k < M; k += 16)
                rank += (d_keys[k] < key) ? 1 : 0;
            rank += __shfl_xor_sync(0xffffffffu, rank, 1);
            rank += __shfl_xor_sync(0xffffffffu, rank, 2);
            rank += __shfl_xor_sync(0xffffffffu, rank, 4);
            rank += __shfl_xor_sync(0xffffffffu, rank, 8);

            if (sub == 0 && rank < TOPK) {
                unsigned long long k0 = ~key;
                unsigned bits = (unsigned)(k0 >> 32);
                unsigned aidx = 0xFFFFFFFFu - (unsigned)(k0 & 0xFFFFFFFFull);
                float score = __uint_as_float(bits);
                int   lab   = (int)d_label[aidx];

                const float CLAMPF = 6.907755278982137f;   // log(1000)
                float4 r4 = reinterpret_cast<const float4*>(reg)[aidx];
                float e0 = __nv_expf(fminf(r4.x, CLAMPF));
                float e1 = __nv_expf(fminf(r4.y, CLAMPF));
                float e2 = __nv_expf(fminf(r4.z, CLAMPF));
                float e3 = __nv_expf(fminf(r4.w, CLAMPF));
                float ax = (float)(aidx % FMP);
                float ay = (float)(aidx / FMP);
                float b0 = fminf(1.0f, fmaxf(0.0f, __fdiv_rn(__fmul_rn(__fadd_rn(ax, -e0), 4.0f), 1280.0f)));
                float b1 = fminf(1.0f, fmaxf(0.0f, __fdiv_rn(__fmul_rn(__fadd_rn(ay, -e1), 4.0f), 1280.0f)));
                float b2 = fminf(1.0f, fmaxf(0.0f, __fdiv_rn(__fmul_rn(__fadd_rn(ax,  e2), 4.0f), 1280.0f)));
                float b3 = fminf(1.0f, fmaxf(0.0f, __fdiv_rn(__fmul_rn(__fadd_rn(ay,  e3), 4.0f), 1280.0f)));

                out[rank]        = score;
                out[TOPK + rank] = (float)lab;
                reinterpret_cast<float4*>(out + 2 * TOPK)[rank] = make_float4(b0, b1, b2, b3);
                d_boxes4[rank] = make_float4(b0, b1, b2, b3);
                d_tlab[rank]   = lab;
            }
        }
    }
    gbar(3);

    // ======== S4: suppression rows, compacted (block-per-row) ================
    for (int i = blk; i < TOPK; i += NBLK) {
        int j = tid; int w = tid >> 5;
        float4 bxi = d_boxes4[i];
        float ai = __fmul_rn(__fadd_rn(bxi.z, -bxi.x), __fadd_rn(bxi.w, -bxi.y));
        int li = d_tlab[i];

        bool sup = false;
        if (j < TOPK && j > i && d_tlab[j] == li) {
            float4 bxj = d_boxes4[j];
            float aj = __fmul_rn(__fadd_rn(bxj.z, -bxj.x), __fadd_rn(bxj.w, -bxj.y));
            float wd = fmaxf(1e-10f, __fadd_rn(fminf(bxi.z, bxj.z), -fmaxf(bxi.x, bxj.x)));
            float hd = fmaxf(1e-10f, __fadd_rn(fminf(bxi.w, bxj.w), -fmaxf(bxi.y, bxj.y)));
            float inter = __fmul_rn(wd, hd);
            float den = __fadd_rn(__fadd_rn(__fadd_rn(ai, aj), -inter), 1e-10f);
            // rn32(inter/den) > 0.6f  <=>  inter/den > midpoint(0.6f, nextup(0.6f))
            sup = ((double)inter / (double)den) > 0.6000000536441802978515625;
        }
        unsigned b = __ballot_sync(0xffffffffu, sup);
        if ((j & 31) == 0) tmp[w] = b;
        __syncthreads();
        if (tid < 32) {
            unsigned x = tmp[tid];
            unsigned anyb = __ballot_sync(0xffffffffu, x != 0u);
            if (anyb) {
                int slot = 0;
                if (tid == 0) {
                    slot = atomicAdd(&g.nnz, 1);
                    d_rowslot[i] = slot;
                    atomicOr(&g.nzmask[i >> 5], 1u << (i & 31));
                }
                slot = __shfl_sync(0xffffffffu, slot, 0);
                d_rowdata[slot * 32 + tid] = x;
            }
        }
        __syncthreads();
    }
    gbar(4);

    // ======== S5: greedy NMS over compact rows (block 0) =====================
    if (blk != 0) return;
    {
        int nnz = g.nnz;
        int stagen = nnz < STAGE ? nnz : STAGE;
        for (int t = tid; t < stagen * 32; t += 1024) sstage[t] = d_rowdata[t];
        for (int t = tid; t < TOPK; t += 1024)        sslot[t]  = d_rowslot[t];
        __syncthreads();

        if (tid < 32) {
            unsigned keep = 0xFFFFFFFFu;         // lane ln holds keep bits [ln*32..]
            unsigned nzm  = g.nzmask[lane];
            for (int wi = 0; wi < 32; ++wi) {
                unsigned bits = __shfl_sync(0xffffffffu, nzm, wi);
                while (bits) {
                    int bpos = __ffs(bits) - 1;
                    bits &= bits - 1u;
                    unsigned kw = __shfl_sync(0xffffffffu, keep, wi);
                    if ((kw >> bpos) & 1u) {
                        int i = wi * 32 + bpos;
                        int slot = sslot[i];     // shared, warp-uniform
                        unsigned roww = (slot < STAGE) ? sstage[slot * 32 + lane]
                                                       : d_rowdata[slot * 32 + lane];
                        keep &= ~roww;
                    }
                }
            }
            skeep[lane] = keep;
        }
        __syncthreads();
        if (tid < TOPK)
            out[6 * TOPK + tid] = (float)((skeep[tid >> 5] >> (tid & 31)) & 1u);
    }
}

// ---------------- launch ----------------
extern "C" void kernel_launch(void* const* d_in, const int* in_sizes, int n_in,
                              void* d_out, int out_size) {
    const float* hmp = (const float*)d_in[0];
    const float* reg = (const float*)d_in[1];
    const float* iou = (const float*)d_in[2];
    float* out = (float*)d_out;

    void* gptr = nullptr;
    cudaGetSymbolAddress(&gptr, g);
    cudaMemsetAsync(gptr, 0, sizeof(GState), 0);

    k_score<<<N_ANCH / 64, 256>>>(hmp, iou);
    k_mega<<<NBLK, 1024>>>(reg, out);
}

// round 17
// speedup vs baseline: 2.4779x; 1.0708x over previous
#include <cuda_runtime.h>
#include <cuda_bf16.h>
#include <math.h>

#define N_ANCH   102400
#define FMP      320
#define NCLS     80
#define TOPK     1000
#define CAP      4096
#define NBINS    65536
#define NPART    64
#define NBLK     148
#define STAGE    192             // rows staged in shared for NMS

// libdevice precise expf — the exact function XLA:GPU links for HLO exp(f32).
extern "C" __device__ float __nv_expf(float);

// ------- state that must be zero at the start of every replay (ONE memset) --
struct GState {
    unsigned int hist[NBINS];
    unsigned int bars[8];
    unsigned int nzmask[32];     // 1000-bit bitmap of rows with nonzero mask
    int          count;
    int          nnz;
};
__device__ GState g;

// ------- scratch fully written-before-read each replay -----------------------
__device__ __align__(16) unsigned int      d_sbits[N_ANCH];
__device__ unsigned char                   d_label[N_ANCH];
__device__ unsigned long long              d_keys[CAP];
__device__ float4                          d_boxes4[TOPK];
__device__ int                             d_tlab[TOPK];
__device__ int                             d_rowslot[TOPK];
__device__ unsigned int                    d_rowdata[TOPK * 32];
__device__ unsigned int                    d_part[NPART];
__device__ int                             d_thresh;

// XLA LogisticExpander: logistic(x) = 1/(1+exp(-x)), exp->__nv_expf, div->rn.
__device__ __forceinline__ float xsig(float x) {
    return __fdiv_rn(1.0f, __fadd_rn(1.0f, __nv_expf(-x)));
}
__device__ __forceinline__ float xfused(float h, float K) {
    return __fsqrt_rn(__fmul_rn(xsig(h), K));
}

// ---------------- K1: scores — 8 anchors/warp, 4 lanes/anchor ---------------
// Branchless fast path: per lane, exactly-one-candidate implies the candidate
// is the lane max at its first index, so ONE xfused(m_l) evaluation (computed
// unconditionally by all lanes — no divergent branch) reproduces the old
// per-candidate scan bit-exactly. >=2 candidates in a lane (~1e-4 probability
// per anchor) falls back to the verbatim R16 CHK chain, warp-uniform branch.
__global__ void __launch_bounds__(256)
k_score(const float* __restrict__ hmp, const float* __restrict__ iou) {
    const int wid  = threadIdx.x >> 5;            // warp in block: 0..7
    const int lane = threadIdx.x & 31;
    const int grp  = lane >> 2;                   // anchor group 0..7
    const int sub  = lane & 3;                    // lane within group
    const int base = (blockIdx.x << 6) + (wid << 3);   // 8 anchors per warp
    const int a    = base + grp;

    // iou for the 8 anchors: lanes 0..7 load, broadcast to groups
    float iv = 0.0f;
    if (lane < 8) iv = iou[base + lane];
    float ivg = __shfl_sync(0xffffffffu, iv, grp);

    // each lane: 5 float4 = 20 classes [sub*20, sub*20+20)
    const float4* row = reinterpret_cast<const float4*>(hmp) + (size_t)a * 20 + sub * 5;
    float4 v0 = row[0], v1 = row[1], v2 = row[2], v3 = row[3], v4 = row[4];

    float m_l = fmaxf(fmaxf(v0.x, v0.y), fmaxf(v0.z, v0.w));
    m_l = fmaxf(m_l, fmaxf(fmaxf(v1.x, v1.y), fmaxf(v1.z, v1.w)));
    m_l = fmaxf(m_l, fmaxf(fmaxf(v2.x, v2.y), fmaxf(v2.z, v2.w)));
    m_l = fmaxf(m_l, fmaxf(fmaxf(v3.x, v3.y), fmaxf(v3.z, v3.w)));
    m_l = fmaxf(m_l, fmaxf(fmaxf(v4.x, v4.y), fmaxf(v4.z, v4.w)));
    float m = fmaxf(m_l, __shfl_xor_sync(0xffffffffu, m_l, 1));
    m = fmaxf(m, __shfl_xor_sync(0xffffffffu, m, 2));

    float K   = xsig(ivg);
    float thr = m - 1e-4f;

    // candidate count + first index of lane max (branchless selects)
    int cnt = 0, idx = 0x7FFFFFFF;
    #define SCAN(val, i) \
        cnt += ((val) >= thr) ? 1 : 0; \
        idx  = min(idx, ((val) == m_l) ? (i) : 0x7FFFFFFF);
    SCAN(v0.x, 0)  SCAN(v0.y, 1)  SCAN(v0.z, 2)  SCAN(v0.w, 3)
    SCAN(v1.x, 4)  SCAN(v1.y, 5)  SCAN(v1.z, 6)  SCAN(v1.w, 7)
    SCAN(v2.x, 8)  SCAN(v2.y, 9)  SCAN(v2.z, 10) SCAN(v2.w, 11)
    SCAN(v3.x, 12) SCAN(v3.y, 13) SCAN(v3.z, 14) SCAN(v3.w, 15)
    SCAN(v4.x, 16) SCAN(v4.y, 17) SCAN(v4.z, 18) SCAN(v4.w, 19)
    #undef SCAN

    const int cb = sub * 20;
    float best;
    int   bi;
    if (__any_sync(0xffffffffu, cnt >= 2)) {
        // ---- rare slow path: verbatim R16 chain (bit-exact semantics) ----
        best = __int_as_float(0xff800000);
        bi   = 0x7FFFFFFF;
        #define CHK(val, i) \
            if ((val) >= thr) { float f = xfused((val), K); \
                                if (f > best) { best = f; bi = cb + (i); } }
        CHK(v0.x, 0)  CHK(v0.y, 1)  CHK(v0.z, 2)  CHK(v0.w, 3)
        CHK(v1.x, 4)  CHK(v1.y, 5)  CHK(v1.z, 6)  CHK(v1.w, 7)
        CHK(v2.x, 8)  CHK(v2.y, 9)  CHK(v2.z, 10) CHK(v2.w, 11)
        CHK(v3.x, 12) CHK(v3.y, 13) CHK(v3.z, 14) CHK(v3.w, 15)
        CHK(v4.x, 16) CHK(v4.y, 17) CHK(v4.z, 18) CHK(v4.w, 19)
        #undef CHK
    } else {
        // ---- fast path: single unconditional eval, no divergence ----
        float f  = xfused(m_l, K);
        bool has = (m_l >= thr);             // cnt>=1  <=>  m_l>=thr
        best = has ? f : __int_as_float(0xff800000);
        bi   = has ? (cb + idx) : 0x7FFFFFFF;
    }

    #pragma unroll
    for (int off = 1; off <= 2; off <<= 1) {
        float of = __shfl_xor_sync(0xffffffffu, best, off);
        int   oi = __shfl_xor_sync(0xffffffffu, bi,   off);
        if (of > best || (of == best && oi < bi)) { best = of; bi = oi; }
    }

    if (sub == 0) {
        unsigned bits = __float_as_uint(best);
        d_sbits[a] = bits;
        d_label[a] = (unsigned char)bi;
        atomicAdd(&g.hist[bits >> 16], 1u);
    }
}

// ---------------- software grid barrier (all 148 blocks resident) -----------
__device__ __forceinline__ void gbar(int which) {
    __syncthreads();
    if (threadIdx.x == 0) {
        __threadfence();
        unsigned arrived = atomicAdd(&g.bars[which], 1u) + 1u;
        if (arrived < NBLK) {
            volatile unsigned* c = &g.bars[which];
            while (*c < NBLK) __nanosleep(32);
        }
        __threadfence();
    }
    __syncthreads();
}

// ---------------- K2: mega — R16 structure + smem-staged S3 keys ------------
__global__ void __launch_bounds__(1024, 1)
k_mega(const float* __restrict__ reg, float* __restrict__ out) {
    __shared__ unsigned spart[NPART];
    __shared__ unsigned wtot[32];
    __shared__ unsigned whi[32];
    __shared__ int      s_pstar;
    __shared__ unsigned s_above;
    __shared__ unsigned tmp[32];
    __shared__ int      sslot[TOPK];
    __shared__ unsigned long long skeys[CAP];   // S3 keys; aliased by S5 stage
    __shared__ unsigned skeep[32];

    unsigned* sstage = reinterpret_cast<unsigned*>(skeys);  // S5 reuse (24KB<=32KB)

    const int tid  = threadIdx.x;
    const int blk  = blockIdx.x;
    const int gt   = blk * 1024 + tid;
    const int lane = tid & 31;

    // ======== S0: per-part histogram sums (blocks 0..63) =====================
    if (blk < NPART) {
        unsigned v = g.hist[blk * 1024 + tid];
        #pragma unroll
        for (int off = 16; off; off >>= 1) v += __shfl_xor_sync(0xffffffffu, v, off);
        if ((tid & 31) == 0) wtot[tid >> 5] = v;
        __syncthreads();
        if (tid < 32) {
            unsigned w = wtot[tid];
            #pragma unroll
            for (int off = 16; off; off >>= 1) w += __shfl_xor_sync(0xffffffffu, w, off);
            if (tid == 0) d_part[blk] = w;
        }
    }
    gbar(0);

    // ======== S1: exact 16-bit threshold (block 0, fully parallel) ==========
    if (blk == 0) {
        if (tid < NPART) spart[tid] = d_part[tid];
        __syncthreads();
        if (tid < 32) {
            unsigned a = spart[tid], b = spart[tid + 32];
            unsigned sa = a, sb = b;
            #pragma unroll
            for (int off = 1; off < 32; off <<= 1) {
                unsigned ta = __shfl_down_sync(0xffffffffu, sa, off);
                unsigned tb = __shfl_down_sync(0xffffffffu, sb, off);
                if (tid + off < 32) { sa += ta; sb += tb; }
            }
            unsigned totb = __shfl_sync(0xffffffffu, sb, 0);
            unsigned sufa = sa + totb;           // inclusive suffix at p=tid
            unsigned sufb = sb;                  // inclusive suffix at p=tid+32
            if (sufa >= TOPK && sufa - a < TOPK) { s_pstar = tid;      s_above = sufa - a; }
            if (sufb >= TOPK && sufb - b < TOPK) { s_pstar = tid + 32; s_above = sufb - b; }
        }
        __syncthreads();
        int base = s_pstar << 10;
        int w = tid >> 5;
        unsigned own = g.hist[base + tid];
        unsigned s = own;
        #pragma unroll
        for (int off = 1; off < 32; off <<= 1) {
            unsigned t = __shfl_down_sync(0xffffffffu, s, off);
            if (lane + off < 32) s += t;
        }
        if (lane == 0) wtot[w] = s;
        __syncthreads();
        if (tid < 32) {
            unsigned v = wtot[tid];
            unsigned sv = v;
            #pragma unroll
            for (int off = 1; off < 32; off <<= 1) {
                unsigned t = __shfl_down_sync(0xffffffffu, sv, off);
                if (tid + off < 32) sv += t;
            }
            whi[tid] = sv - v;                   // totals of warps above mine
        }
        __syncthreads();
        unsigned tot = s_above + whi[w] + s;     // count of scores >= this bin
        if (tot >= TOPK && tot - own < TOPK) d_thresh = base + tid;
    }
    gbar(1);

    // ======== S2: compact candidates =========================================
    {
        int th = d_thresh;
        for (int t = gt; t < N_ANCH / 4; t += NBLK * 1024) {
            uint4 s = reinterpret_cast<const uint4*>(d_sbits)[t];
            unsigned a = (unsigned)t * 4u;
            #pragma unroll
            for (int q = 0; q < 4; ++q) {
                unsigned bits = (q == 0) ? s.x : (q == 1) ? s.y : (q == 2) ? s.z : s.w;
                if ((int)(bits >> 16) >= th) {
                    int pos = atomicAdd(&g.count, 1);
                    if (pos < CAP) {
                        unsigned long long key =
                            ((unsigned long long)bits << 32) |
                            (unsigned long long)(0xFFFFFFFFu - (a + q));
                        d_keys[pos] = ~key;
                    }
                }
            }
        }
    }
    gbar(2);

    // ======== S3: rank-by-counting + decode (keys staged in shared) ==========
    {
        int M = g.count; if (M > CAP) M = CAP;
        if (blk * 64 < M) {                      // only blocks owning candidates
            for (int t = tid; t < M; t += 1024) skeys[t] = d_keys[t];
            __syncthreads();

            int cand = gt >> 4;
            int sub  = gt & 15;
            if (cand < M) {
                unsigned long long key = skeys[cand];
                int rank = 0;
                for (int k = sub; k < M; k += 16)
                    rank += (skeys[k] < key) ? 1 : 0;
                rank += __shfl_xor_sync(0xffffffffu, rank, 1);
                rank += __shfl_xor_sync(0xffffffffu, rank, 2);
                rank += __shfl_xor_sync(0xffffffffu, rank, 4);
                rank += __shfl_xor_sync(0xffffffffu, rank, 8);

                if (sub == 0 && rank < TOPK) {
                    unsigned long long k0 = ~key;
                    unsigned bits = (unsigned)(k0 >> 32);
                    unsigned aidx = 0xFFFFFFFFu - (unsigned)(k0 & 0xFFFFFFFFull);
                    float score = __uint_as_float(bits);
                    int   lab   = (int)d_label[aidx];

                    const float CLAMPF = 6.907755278982137f;   // log(1000)
                    float4 r4 = reinterpret_cast<const float4*>(reg)[aidx];
                    float e0 = __nv_expf(fminf(r4.x, CLAMPF));
                    float e1 = __nv_expf(fminf(r4.y, CLAMPF));
                    float e2 = __nv_expf(fminf(r4.z, CLAMPF));
                    float e3 = __nv_expf(fminf(r4.w, CLAMPF));
                    float ax = (float)(aidx % FMP);
                    float ay = (float)(aidx / FMP);
                    float b0 = fminf(1.0f, fmaxf(0.0f, __fdiv_rn(__fmul_rn(__fadd_rn(ax, -e0), 4.0f), 1280.0f)));
                    float b1 = fminf(1.0f, fmaxf(0.0f, __fdiv_rn(__fmul_rn(__fadd_rn(ay, -e1), 4.0f), 1280.0f)));
                    float b2 = fminf(1.0f, fmaxf(0.0f, __fdiv_rn(__fmul_rn(__fadd_rn(ax,  e2), 4.0f), 1280.0f)));
                    float b3 = fminf(1.0f, fmaxf(0.0f, __fdiv_rn(__fmul_rn(__fadd_rn(ay,  e3), 4.0f), 1280.0f)));

                    out[rank]        = score;
                    out[TOPK + rank] = (float)lab;
                    reinterpret_cast<float4*>(out + 2 * TOPK)[rank] = make_float4(b0, b1, b2, b3);
                    d_boxes4[rank] = make_float4(b0, b1, b2, b3);
                    d_tlab[rank]   = lab;
                }
            }
        }
    }
    gbar(3);

    // ======== S4: suppression rows, compacted (block-per-row) ================
    for (int i = blk; i < TOPK; i += NBLK) {
        int j = tid; int w = tid >> 5;
        float4 bxi = d_boxes4[i];
        float ai = __fmul_rn(__fadd_rn(bxi.z, -bxi.x), __fadd_rn(bxi.w, -bxi.y));
        int li = d_tlab[i];

        bool sup = false;
        if (j < TOPK && j > i && d_tlab[j] == li) {
            float4 bxj = d_boxes4[j];
            float aj = __fmul_rn(__fadd_rn(bxj.z, -bxj.x), __fadd_rn(bxj.w, -bxj.y));
            float wd = fmaxf(1e-10f, __fadd_rn(fminf(bxi.z, bxj.z), -fmaxf(bxi.x, bxj.x)));
            float hd = fmaxf(1e-10f, __fadd_rn(fminf(bxi.w, bxj.w), -fmaxf(bxi.y, bxj.y)));
            float inter = __fmul_rn(wd, hd);
            float den = __fadd_rn(__fadd_rn(__fadd_rn(ai, aj), -inter), 1e-10f);
            // rn32(inter/den) > 0.6f  <=>  inter/den > midpoint(0.6f, nextup(0.6f))
            sup = ((double)inter / (double)den) > 0.6000000536441802978515625;
        }
        unsigned b = __ballot_sync(0xffffffffu, sup);
        if ((j & 31) == 0) tmp[w] = b;
        __syncthreads();
        if (tid < 32) {
            unsigned x = tmp[tid];
            unsigned anyb = __ballot_sync(0xffffffffu, x != 0u);
            if (anyb) {
                int slot = 0;
                if (tid == 0) {
                    slot = atomicAdd(&g.nnz, 1);
                    d_rowslot[i] = slot;
                    atomicOr(&g.nzmask[i >> 5], 1u << (i & 31));
                }
                slot = __shfl_sync(0xffffffffu, slot, 0);
                d_rowdata[slot * 32 + tid] = x;
            }
        }
        __syncthreads();
    }
    gbar(4);

    // ======== S5: greedy NMS over compact rows (block 0) =====================
    if (blk != 0) return;
    {
        int nnz = g.nnz;
        int stagen = nnz < STAGE ? nnz : STAGE;
        for (int t = tid; t < stagen * 32; t += 1024) sstage[t] = d_rowdata[t];
        for (int t = tid; t < TOPK; t += 1024)        sslot[t]  = d_rowslot[t];
        __syncthreads();

        if (tid < 32) {
            unsigned keep = 0xFFFFFFFFu;         // lane ln holds keep bits [ln*32..]
            unsigned nzm  = g.nzmask[lane];
            for (int wi = 0; wi < 32; ++wi) {
                unsigned bits = __shfl_sync(0xffffffffu, nzm, wi);
                while (bits) {
                    int bpos = __ffs(bits) - 1;
                    bits &= bits - 1u;
                    unsigned kw = __shfl_sync(0xffffffffu, keep, wi);
                    if ((kw >> bpos) & 1u) {
                        int i = wi * 32 + bpos;
                        int slot = sslot[i];     // shared, warp-uniform
                        unsigned roww = (slot < STAGE) ? sstage[slot * 32 + lane]
                                                       : d_rowdata[slot * 32 + lane];
                        keep &= ~roww;
                    }
                }
            }
            skeep[lane] = keep;
        }
        __syncthreads();
        if (tid < TOPK)
            out[6 * TOPK + tid] = (float)((skeep[tid >> 5] >> (tid & 31)) & 1u);
    }
}

// ---------------- launch ----------------
extern "C" void kernel_launch(void* const* d_in, const int* in_sizes, int n_in,
                              void* d_out, int out_size) {
    const float* hmp = (const float*)d_in[0];
    const float* reg = (const float*)d_in[1];
    const float* iou = (const float*)d_in[2];
    float* out = (float*)d_out;

    void* gptr = nullptr;
    cudaGetSymbolAddress(&gptr, g);
    cudaMemsetAsync(gptr, 0, sizeof(GState), 0);

    k_score<<<N_ANCH / 64, 256>>>(hmp, iou);
    k_mega<<<NBLK, 1024>>>(reg, out);
}